// round 1
// baseline (speedup 1.0000x reference)
#include <cuda_runtime.h>

// Problem constants (fixed by setup_inputs)
#define NB 8
#define CH 256
#define DD 8
#define HH 16
#define WW 16
#define PP 2048   // DD*HH*WW

// Scratch (no allocations allowed): per-(n,c) partial dot sums + per-n mask counts
__device__ float g_partials[NB * CH];
__device__ int   g_counts[NB];

// Non-contractable f32 ops so the mask predicate matches plain IEEE f32
// (no FMA contraction, matching the reference's elementwise mul/add chain).
__device__ __forceinline__ float fm(float a, float b) { return __fmul_rn(a, b); }
__device__ __forceinline__ float fa(float a, float b) { return __fadd_rn(a, b); }
__device__ __forceinline__ float fs(float a, float b) { return __fsub_rn(a, b); }

__global__ void __launch_bounds__(256) pixpro_main(
    const float* __restrict__ q,
    const float* __restrict__ k,
    const float* __restrict__ cq,
    const float* __restrict__ ck)
{
    const int bx  = blockIdx.x;      // 0 .. NB*CH-1
    const int n   = bx >> 8;         // batch
    const int c   = bx & 255;        // channel
    const int tid = threadIdx.x;

    __shared__ float ks[PP];                     // k[n,c,:] slice (8KB)
    __shared__ float s_cqx[WW], s_ckx[WW];
    __shared__ float s_cqy[HH], s_cky[HH];
    __shared__ float s_cqz[DD], s_ckz[DD];
    __shared__ float s_red[256];
    __shared__ int   s_cnt[256];

    // --- Geometry (every thread computes; all identical, cheap) ---
    const float x0q = cq[n * 6 + 0], y0q = cq[n * 6 + 1], z0q = cq[n * 6 + 2];
    const float x1q = cq[n * 6 + 3], y1q = cq[n * 6 + 4], z1q = cq[n * 6 + 5];
    const float x0k = ck[n * 6 + 0], y0k = ck[n * 6 + 1], z0k = ck[n * 6 + 2];
    const float x1k = ck[n * 6 + 3], y1k = ck[n * 6 + 4], z1k = ck[n * 6 + 5];

    const float bwq = __fdiv_rn(fs(x1q, x0q), (float)WW);
    const float bhq = __fdiv_rn(fs(y1q, y0q), (float)HH);
    const float bdq = __fdiv_rn(fs(z1q, z0q), (float)DD);
    const float bwk = __fdiv_rn(fs(x1k, x0k), (float)WW);
    const float bhk = __fdiv_rn(fs(y1k, y0k), (float)HH);
    const float bdk = __fdiv_rn(fs(z1k, z0k), (float)DD);

    const float diag_q = __fsqrt_rn(fa(fa(fm(bwq, bwq), fm(bhq, bhq)), fm(bdq, bdq)));
    const float diag_k = __fsqrt_rn(fa(fa(fm(bwk, bwk), fm(bhk, bhk)), fm(bdk, bdk)));
    const float maxdiag = fmaxf(diag_q, diag_k);

    // Candidate-window half-widths (slightly widened; exact predicate filters inside)
    const float r   = 0.5f * maxdiag;
    const float hx  = r / bwk + 0.02f;
    const float hy  = r / bhk + 0.02f;
    const float hz  = r / bdk + 0.02f;
    const float ibwk = 1.0f / bwk;
    const float ibhk = 1.0f / bhk;
    const float ibdk = 1.0f / bdk;

    // --- Center tables (match reference arithmetic: (i+0.5)*b + origin) ---
    if (tid < WW) {
        s_cqx[tid] = fa(fm((float)tid + 0.5f, bwq), x0q);
        s_ckx[tid] = fa(fm((float)tid + 0.5f, bwk), x0k);
    }
    if (tid < HH) {
        s_cqy[tid] = fa(fm((float)tid + 0.5f, bhq), y0q);
        s_cky[tid] = fa(fm((float)tid + 0.5f, bhk), y0k);
    }
    if (tid < DD) {
        s_cqz[tid] = fa(fm((float)tid + 0.5f, bdq), z0q);
        s_ckz[tid] = fa(fm((float)tid + 0.5f, bdk), z0k);
    }

    // --- Stage k slice into SMEM (coalesced) ---
    const float* __restrict__ kp = k + (size_t)(n * CH + c) * PP;
    #pragma unroll
    for (int i = tid; i < PP; i += 256) ks[i] = kp[i];
    __syncthreads();

    // --- Per-thread work: 8 voxels each ---
    const float* __restrict__ qp = q + (size_t)(n * CH + c) * PP;
    float local = 0.0f;
    int   lcnt  = 0;

    #pragma unroll
    for (int pi = 0; pi < PP / 256; pi++) {
        const int p  = tid + pi * 256;
        const int ix = p & 15;
        const int iy = (p >> 4) & 15;
        const int iz = p >> 8;

        const float cxv = s_cqx[ix];
        const float cyv = s_cqy[iy];
        const float czv = s_cqz[iz];

        // windows: k index j such that |cq - ck[j]| may be < r
        const float txc = (cxv - x0k) * ibwk - 0.5f;
        const float tyc = (cyv - y0k) * ibhk - 0.5f;
        const float tzc = (czv - z0k) * ibdk - 0.5f;
        const int jxlo = max(0, (int)ceilf(txc - hx));
        const int jxhi = min(WW - 1, (int)floorf(txc + hx));
        const int jylo = max(0, (int)ceilf(tyc - hy));
        const int jyhi = min(HH - 1, (int)floorf(tyc + hy));
        const int jzlo = max(0, (int)ceilf(tzc - hz));
        const int jzhi = min(DD - 1, (int)floorf(tzc + hz));

        float acc = 0.0f;
        for (int jz = jzlo; jz <= jzhi; jz++) {
            const float dz  = fs(czv, s_ckz[jz]);
            const float dz2 = fm(dz, dz);
            const int baseZ = jz << 8;
            for (int jy = jylo; jy <= jyhi; jy++) {
                const float dy  = fs(cyv, s_cky[jy]);
                const float dy2 = fm(dy, dy);
                const int baseY = baseZ + (jy << 4);
                for (int jx = jxlo; jx <= jxhi; jx++) {
                    const float dx = fs(cxv, s_ckx[jx]);
                    // reference order: (dx^2 + dy^2) + dz^2, then sqrt, then /max_diag
                    const float s2 = fa(fa(fm(dx, dx), dy2), dz2);
                    if (__fdiv_rn(__fsqrt_rn(s2), maxdiag) < 0.5f) {
                        acc += ks[baseY + jx];
                        lcnt++;
                    }
                }
            }
        }
        local = fmaf(qp[p], acc, local);
    }

    // --- Block reduction (deterministic tree) ---
    s_red[tid] = local;
    s_cnt[tid] = lcnt;
    __syncthreads();
    #pragma unroll
    for (int s = 128; s > 0; s >>= 1) {
        if (tid < s) {
            s_red[tid] += s_red[tid + s];
            s_cnt[tid] += s_cnt[tid + s];
        }
        __syncthreads();
    }
    if (tid == 0) {
        g_partials[bx] = s_red[0];
        if (c == 0) g_counts[n] = s_cnt[0];  // mask count is channel-independent
    }
}

__global__ void pixpro_final(float* __restrict__ out)
{
    __shared__ float losses[NB];
    const int t = threadIdx.x;
    if (t < NB) {
        float s = 0.0f;
        for (int i = 0; i < CH; i++) s += g_partials[t * CH + i];  // fixed order
        losses[t] = s / ((float)g_counts[t] + 1e-6f);
    }
    __syncthreads();
    if (t == 0) {
        float m = 0.0f;
        for (int i = 0; i < NB; i++) m += losses[i];
        out[0] = -2.0f * (m * (1.0f / (float)NB));
    }
}

extern "C" void kernel_launch(void* const* d_in, const int* in_sizes, int n_in,
                              void* d_out, int out_size)
{
    const float* q  = (const float*)d_in[0];
    const float* k  = (const float*)d_in[1];
    const float* cq = (const float*)d_in[2];
    const float* ck = (const float*)d_in[3];
    float* out = (float*)d_out;

    pixpro_main<<<NB * CH, 256>>>(q, k, cq, ck);
    pixpro_final<<<1, 32>>>(out);
}

// round 2
// speedup vs baseline: 1.8295x; 1.8295x over previous
#include <cuda_runtime.h>

// Problem constants (fixed by setup_inputs)
#define NB 8
#define CH 256
#define DD 8
#define HH 16
#define WW 16
#define PP 2048   // DD*HH*WW

// Scratch (no allocations allowed)
__device__ float g_partials[NB * CH];           // per-(n,c) dot partials
__device__ int   g_blkcnt[NB * 8];              // per-maskblock candidate counts
// Per-voxel run records: 8 x u16 per voxel:
//   slot0 = nruns; slots1..7 = run: bits[0:11)=base k-index, bits[11:13)=len (1..3)
__device__ __align__(16) unsigned short g_runs16[NB * PP * 8];

// Non-contractable f32 ops so the mask predicate matches plain IEEE f32
__device__ __forceinline__ float fm(float a, float b) { return __fmul_rn(a, b); }
__device__ __forceinline__ float fa(float a, float b) { return __fadd_rn(a, b); }
__device__ __forceinline__ float fs(float a, float b) { return __fsub_rn(a, b); }

// ---------------- Kernel A: build mask runs (geometry only, once per n) -------------
__global__ void __launch_bounds__(256) pixpro_mask(
    const float* __restrict__ cq, const float* __restrict__ ck)
{
    const int n   = blockIdx.x >> 3;                 // 8 blocks per batch
    const int tid = threadIdx.x;
    const int p   = ((blockIdx.x & 7) << 8) + tid;   // one voxel per thread

    // Geometry (exact reference arithmetic)
    const float x0q = cq[n * 6 + 0], y0q = cq[n * 6 + 1], z0q = cq[n * 6 + 2];
    const float x1q = cq[n * 6 + 3], y1q = cq[n * 6 + 4], z1q = cq[n * 6 + 5];
    const float x0k = ck[n * 6 + 0], y0k = ck[n * 6 + 1], z0k = ck[n * 6 + 2];
    const float x1k = ck[n * 6 + 3], y1k = ck[n * 6 + 4], z1k = ck[n * 6 + 5];

    const float bwq = __fdiv_rn(fs(x1q, x0q), (float)WW);
    const float bhq = __fdiv_rn(fs(y1q, y0q), (float)HH);
    const float bdq = __fdiv_rn(fs(z1q, z0q), (float)DD);
    const float bwk = __fdiv_rn(fs(x1k, x0k), (float)WW);
    const float bhk = __fdiv_rn(fs(y1k, y0k), (float)HH);
    const float bdk = __fdiv_rn(fs(z1k, z0k), (float)DD);

    const float diag_q = __fsqrt_rn(fa(fa(fm(bwq, bwq), fm(bhq, bhq)), fm(bdq, bdq)));
    const float diag_k = __fsqrt_rn(fa(fa(fm(bwk, bwk), fm(bhk, bhk)), fm(bdk, bdk)));
    const float maxdiag = fmaxf(diag_q, diag_k);

    const float r  = 0.5f * maxdiag;
    const float hx = r / bwk + 0.02f;
    const float hy = r / bhk + 0.02f;
    const float hz = r / bdk + 0.02f;

    const int ix = p & 15, iy = (p >> 4) & 15, iz = p >> 8;
    const float cxv = fa(fm((float)ix + 0.5f, bwq), x0q);
    const float cyv = fa(fm((float)iy + 0.5f, bhq), y0q);
    const float czv = fa(fm((float)iz + 0.5f, bdq), z0q);

    const float txc = (cxv - x0k) / bwk - 0.5f;
    const float tyc = (cyv - y0k) / bhk - 0.5f;
    const float tzc = (czv - z0k) / bdk - 0.5f;
    const int jxlo = max(0, (int)ceilf(txc - hx));
    const int jxhi = min(WW - 1, (int)floorf(txc + hx));
    const int jylo = max(0, (int)ceilf(tyc - hy));
    const int jyhi = min(HH - 1, (int)floorf(tyc + hy));
    const int jzlo = max(0, (int)ceilf(tzc - hz));
    const int jzhi = min(DD - 1, (int)floorf(tzc + hz));

    const int base16 = (n * PP + p) * 8;
    int nr = 0, cnt = 0;

    for (int jz = jzlo; jz <= jzhi; jz++) {
        const float dz  = fs(czv, fa(fm((float)jz + 0.5f, bdk), z0k));
        const float dz2 = fm(dz, dz);
        for (int jy = jylo; jy <= jyhi; jy++) {
            const float dy  = fs(cyv, fa(fm((float)jy + 0.5f, bhk), y0k));
            const float dy2 = fm(dy, dy);
            int first = -1, last = -2;
            for (int jx = jxlo; jx <= jxhi; jx++) {
                const float dx = fs(cxv, fa(fm((float)jx + 0.5f, bwk), x0k));
                const float s2 = fa(fa(fm(dx, dx), dy2), dz2);
                if (__fdiv_rn(__fsqrt_rn(s2), maxdiag) < 0.5f) {
                    if (first < 0) first = jx;
                    last = jx;
                }
            }
            if (first >= 0) {
                const int len = last - first + 1;      // <= 3 (passing x-set is an interval)
                cnt += len;
                nr++;
                g_runs16[base16 + nr] =
                    (unsigned short)(((jz << 8) + (jy << 4) + first) | (len << 11));
            }
        }
    }
    g_runs16[base16] = (unsigned short)nr;

    // Deterministic per-block count reduction
    __shared__ int s_cnt[256];
    s_cnt[tid] = cnt;
    __syncthreads();
    #pragma unroll
    for (int s = 128; s > 0; s >>= 1) {
        if (tid < s) s_cnt[tid] += s_cnt[tid + s];
        __syncthreads();
    }
    if (tid == 0) g_blkcnt[blockIdx.x] = s_cnt[0];
}

// ---------------- Kernel B: masked dot, one block per (n,c) -------------------------
__global__ void __launch_bounds__(256) pixpro_dot(
    const float* __restrict__ q, const float* __restrict__ k)
{
    const int bx  = blockIdx.x;
    const int n   = bx >> 8;
    const int c   = bx & 255;
    const int tid = threadIdx.x;

    __shared__ float ks[PP];
    __shared__ float s_red[256];

    // Stage k slice (vectorized, coalesced)
    const float4* __restrict__ kp4 =
        reinterpret_cast<const float4*>(k + (size_t)(n * CH + c) * PP);
    float4 kv0 = kp4[tid];
    float4 kv1 = kp4[tid + 256];
    reinterpret_cast<float4*>(ks)[tid]       = kv0;
    reinterpret_cast<float4*>(ks)[tid + 256] = kv1;
    __syncthreads();

    // q: 8 contiguous voxels per thread
    const float* __restrict__ qp = q + (size_t)(n * CH + c) * PP;
    const float4 q0 = reinterpret_cast<const float4*>(qp)[tid * 2];
    const float4 q1 = reinterpret_cast<const float4*>(qp)[tid * 2 + 1];
    const float qv[8] = {q0.x, q0.y, q0.z, q0.w, q1.x, q1.y, q1.z, q1.w};

    const uint4* __restrict__ rp =
        reinterpret_cast<const uint4*>(g_runs16) + (size_t)n * PP;

    float local = 0.0f;
    #pragma unroll
    for (int j = 0; j < 8; j++) {
        const int p = tid * 8 + j;
        const uint4 h = rp[p];
        const int nr = (int)(h.x & 0xFFFFu);
        float acc = 0.0f;
        #pragma unroll
        for (int s = 1; s < 8; s++) {
            if (s > nr) break;
            const unsigned w = (s < 2) ? h.x : ((s < 4) ? h.y : ((s < 6) ? h.z : h.w));
            const unsigned run = (s & 1) ? (w >> 16) : (w & 0xFFFFu);
            const int base = (int)(run & 0x7FFu);
            const int len  = (int)((run >> 11) & 0x3u);
            acc += ks[base];
            if (len > 1) acc += ks[base + 1];
            if (len > 2) acc += ks[base + 2];
        }
        local = fmaf(qv[j], acc, local);
    }

    // Deterministic block reduction
    s_red[tid] = local;
    __syncthreads();
    #pragma unroll
    for (int s = 128; s > 0; s >>= 1) {
        if (tid < s) s_red[tid] += s_red[tid + s];
        __syncthreads();
    }
    if (tid == 0) g_partials[bx] = s_red[0];
}

// ---------------- Finalize: one block, warp per batch -------------------------------
__global__ void __launch_bounds__(256) pixpro_final(float* __restrict__ out)
{
    const int tid  = threadIdx.x;
    const int w    = tid >> 5;    // batch index
    const int lane = tid & 31;
    __shared__ float s_loss[NB];

    float s = 0.0f;
    #pragma unroll
    for (int j = 0; j < 8; j++)
        s += g_partials[w * CH + j * 32 + lane];
    #pragma unroll
    for (int off = 16; off > 0; off >>= 1)
        s += __shfl_down_sync(0xFFFFFFFFu, s, off);
    if (lane == 0) {
        int cnt = 0;
        #pragma unroll
        for (int b = 0; b < 8; b++) cnt += g_blkcnt[w * 8 + b];
        s_loss[w] = s / ((float)cnt + 1e-6f);
    }
    __syncthreads();
    if (tid == 0) {
        float m = 0.0f;
        #pragma unroll
        for (int i = 0; i < NB; i++) m += s_loss[i];
        out[0] = -2.0f * (m * (1.0f / (float)NB));
    }
}

extern "C" void kernel_launch(void* const* d_in, const int* in_sizes, int n_in,
                              void* d_out, int out_size)
{
    const float* q  = (const float*)d_in[0];
    const float* k  = (const float*)d_in[1];
    const float* cq = (const float*)d_in[2];
    const float* ck = (const float*)d_in[3];
    float* out = (float*)d_out;

    pixpro_mask<<<NB * 8, 256>>>(cq, ck);
    pixpro_dot<<<NB * CH, 256>>>(q, k);
    pixpro_final<<<1, 256>>>(out);
}

// round 3
// speedup vs baseline: 3.2202x; 1.7602x over previous
#include <cuda_runtime.h>

// Problem constants (fixed by setup_inputs)
#define NB 8
#define CH 256
#define DD 8
#define HH 16
#define WW 16
#define PP 2048   // DD*HH*WW

// Scratch (no allocations allowed)
__device__ float g_partials[NB * CH];           // per-(n,c) dot partials
__device__ int   g_blkcnt[NB * 8];              // per-maskblock candidate counts
// Per-voxel run records: 8 x u16 per voxel:
//   slot0 = nruns; slots1..6 = run: bits[0:11)=base k-index, bits[11:13)=len (1..3)
__device__ __align__(16) unsigned short g_runs16[NB * PP * 8];

// Non-contractable f32 ops so the mask predicate matches plain IEEE f32
__device__ __forceinline__ float fm(float a, float b) { return __fmul_rn(a, b); }
__device__ __forceinline__ float fa(float a, float b) { return __fadd_rn(a, b); }
__device__ __forceinline__ float fs(float a, float b) { return __fsub_rn(a, b); }

// ---------------- Kernel A: build mask runs (geometry only, once per n) -------------
__global__ void __launch_bounds__(256) pixpro_mask(
    const float* __restrict__ cq, const float* __restrict__ ck)
{
    const int n   = blockIdx.x >> 3;                 // 8 blocks per batch
    const int tid = threadIdx.x;
    const int p   = ((blockIdx.x & 7) << 8) + tid;   // one voxel per thread

    // Geometry (exact reference arithmetic)
    const float x0q = cq[n * 6 + 0], y0q = cq[n * 6 + 1], z0q = cq[n * 6 + 2];
    const float x1q = cq[n * 6 + 3], y1q = cq[n * 6 + 4], z1q = cq[n * 6 + 5];
    const float x0k = ck[n * 6 + 0], y0k = ck[n * 6 + 1], z0k = ck[n * 6 + 2];
    const float x1k = ck[n * 6 + 3], y1k = ck[n * 6 + 4], z1k = ck[n * 6 + 5];

    const float bwq = __fdiv_rn(fs(x1q, x0q), (float)WW);
    const float bhq = __fdiv_rn(fs(y1q, y0q), (float)HH);
    const float bdq = __fdiv_rn(fs(z1q, z0q), (float)DD);
    const float bwk = __fdiv_rn(fs(x1k, x0k), (float)WW);
    const float bhk = __fdiv_rn(fs(y1k, y0k), (float)HH);
    const float bdk = __fdiv_rn(fs(z1k, z0k), (float)DD);

    const float diag_q = __fsqrt_rn(fa(fa(fm(bwq, bwq), fm(bhq, bhq)), fm(bdq, bdq)));
    const float diag_k = __fsqrt_rn(fa(fa(fm(bwk, bwk), fm(bhk, bhk)), fm(bdk, bdk)));
    const float maxdiag = fmaxf(diag_q, diag_k);

    const float r  = 0.5f * maxdiag;
    const float hx = r / bwk + 0.02f;
    const float hy = r / bhk + 0.02f;
    const float hz = r / bdk + 0.02f;

    const int ix = p & 15, iy = (p >> 4) & 15, iz = p >> 8;
    const float cxv = fa(fm((float)ix + 0.5f, bwq), x0q);
    const float cyv = fa(fm((float)iy + 0.5f, bhq), y0q);
    const float czv = fa(fm((float)iz + 0.5f, bdq), z0q);

    const float txc = (cxv - x0k) / bwk - 0.5f;
    const float tyc = (cyv - y0k) / bhk - 0.5f;
    const float tzc = (czv - z0k) / bdk - 0.5f;
    const int jxlo = max(0, (int)ceilf(txc - hx));
    const int jxhi = min(WW - 1, (int)floorf(txc + hx));
    const int jylo = max(0, (int)ceilf(tyc - hy));
    const int jyhi = min(HH - 1, (int)floorf(tyc + hy));
    const int jzlo = max(0, (int)ceilf(tzc - hz));
    const int jzhi = min(DD - 1, (int)floorf(tzc + hz));

    const int base16 = (n * PP + p) * 8;
    int nr = 0, cnt = 0;

    for (int jz = jzlo; jz <= jzhi; jz++) {
        const float dz  = fs(czv, fa(fm((float)jz + 0.5f, bdk), z0k));
        const float dz2 = fm(dz, dz);
        for (int jy = jylo; jy <= jyhi; jy++) {
            const float dy  = fs(cyv, fa(fm((float)jy + 0.5f, bhk), y0k));
            const float dy2 = fm(dy, dy);
            int first = -1, last = -2;
            for (int jx = jxlo; jx <= jxhi; jx++) {
                const float dx = fs(cxv, fa(fm((float)jx + 0.5f, bwk), x0k));
                const float s2 = fa(fa(fm(dx, dx), dy2), dz2);
                if (__fdiv_rn(__fsqrt_rn(s2), maxdiag) < 0.5f) {
                    if (first < 0) first = jx;
                    last = jx;
                }
            }
            if (first >= 0) {
                const int len = last - first + 1;      // <= 3 (passing x-set is an interval)
                cnt += len;
                nr++;
                g_runs16[base16 + nr] =
                    (unsigned short)(((jz << 8) + (jy << 4) + first) | (len << 11));
            }
        }
    }
    g_runs16[base16] = (unsigned short)nr;

    // Deterministic per-block count reduction
    __shared__ int s_cnt[256];
    s_cnt[tid] = cnt;
    __syncthreads();
    #pragma unroll
    for (int s = 128; s > 0; s >>= 1) {
        if (tid < s) s_cnt[tid] += s_cnt[tid + s];
        __syncthreads();
    }
    if (tid == 0) g_blkcnt[blockIdx.x] = s_cnt[0];
}

// ---------------- Kernel B: masked dot, one block per (n,c) -------------------------
// Thread tid owns voxels p = tid + 256*j  (lanes consecutive -> conflict-free LDS,
// coalesced run-record and q loads).
__global__ void __launch_bounds__(256) pixpro_dot(
    const float* __restrict__ q, const float* __restrict__ k)
{
    const int bx  = blockIdx.x;
    const int n   = bx >> 8;
    const int c   = bx & 255;
    const int tid = threadIdx.x;

    __shared__ float ks[PP];
    __shared__ float s_wred[8];

    // Stage k slice (vectorized, coalesced)
    const float4* __restrict__ kp4 =
        reinterpret_cast<const float4*>(k + (size_t)(n * CH + c) * PP);
    float4 kv0 = kp4[tid];
    float4 kv1 = kp4[tid + 256];
    reinterpret_cast<float4*>(ks)[tid]       = kv0;
    reinterpret_cast<float4*>(ks)[tid + 256] = kv1;
    __syncthreads();

    const float* __restrict__ qp = q + (size_t)(n * CH + c) * PP;
    const uint4* __restrict__ rp =
        reinterpret_cast<const uint4*>(g_runs16) + (size_t)n * PP;

    float local = 0.0f;
    #pragma unroll
    for (int j = 0; j < 8; j++) {
        const int p = tid + (j << 8);
        const uint4 h  = rp[p];            // coalesced 16B/lane
        const float qv = __ldg(qp + p);    // coalesced 4B/lane
        const int nr = (int)(h.x & 0xFFFFu);
        float acc = 0.0f;
        #pragma unroll
        for (int s = 1; s <= 6; s++) {
            const unsigned w = (s < 2) ? h.x : ((s < 4) ? h.y : ((s < 6) ? h.z : h.w));
            const unsigned run = (s & 1) ? (w >> 16) : (w & 0xFFFFu);
            const int base = (int)(run & 0x7FFu);
            const int len  = (int)((run >> 11) & 0x3u);
            if (s <= nr) {
                acc += ks[base];
                if (len > 1) acc += ks[base + 1];
                if (len > 2) acc += ks[base + 2];
            }
        }
        local = fmaf(qv, acc, local);
    }

    // Deterministic reduction: warp shuffle then cross-warp
    #pragma unroll
    for (int off = 16; off > 0; off >>= 1)
        local += __shfl_down_sync(0xFFFFFFFFu, local, off);
    if ((tid & 31) == 0) s_wred[tid >> 5] = local;
    __syncthreads();
    if (tid == 0) {
        float s = 0.0f;
        #pragma unroll
        for (int w = 0; w < 8; w++) s += s_wred[w];
        g_partials[bx] = s;
    }
}

// ---------------- Finalize: one block, warp per batch -------------------------------
__global__ void __launch_bounds__(256) pixpro_final(float* __restrict__ out)
{
    const int tid  = threadIdx.x;
    const int w    = tid >> 5;    // batch index
    const int lane = tid & 31;
    __shared__ float s_loss[NB];

    float s = 0.0f;
    #pragma unroll
    for (int j = 0; j < 8; j++)
        s += g_partials[w * CH + j * 32 + lane];
    #pragma unroll
    for (int off = 16; off > 0; off >>= 1)
        s += __shfl_down_sync(0xFFFFFFFFu, s, off);
    if (lane == 0) {
        int cnt = 0;
        #pragma unroll
        for (int b = 0; b < 8; b++) cnt += g_blkcnt[w * 8 + b];
        s_loss[w] = s / ((float)cnt + 1e-6f);
    }
    __syncthreads();
    if (tid == 0) {
        float m = 0.0f;
        #pragma unroll
        for (int i = 0; i < NB; i++) m += s_loss[i];
        out[0] = -2.0f * (m * (1.0f / (float)NB));
    }
}

extern "C" void kernel_launch(void* const* d_in, const int* in_sizes, int n_in,
                              void* d_out, int out_size)
{
    const float* q  = (const float*)d_in[0];
    const float* k  = (const float*)d_in[1];
    const float* cq = (const float*)d_in[2];
    const float* ck = (const float*)d_in[3];
    float* out = (float*)d_out;

    pixpro_mask<<<NB * 8, 256>>>(cq, ck);
    pixpro_dot<<<NB * CH, 256>>>(q, k);
    pixpro_final<<<1, 256>>>(out);
}

// round 4
// speedup vs baseline: 3.9832x; 1.2369x over previous
#include <cuda_runtime.h>

// Problem constants (fixed by setup_inputs)
#define NB 8
#define CH 256
#define DD 8
#define HH 16
#define WW 16
#define PP 2048            // DD*HH*WW
#define G  4               // channels per block
#define NBLK (NB * (CH / G))   // 512 blocks
#define NMASK 64               // mask-duty blocks (8 per batch)

// Scratch (no allocations allowed)
__device__ float g_partials[NB * CH];
__device__ int   g_blkcnt[NMASK];
// Per-voxel run records: 8 x u16: slot0=nruns; slots1..6: bits[0:11)=base, [11:13)=len(1..3)
__device__ __align__(16) unsigned short g_runs16[NB * PP * 8];
__device__ int g_mask_flag;   // 0 at start of every launch (self-reset at end)
__device__ int g_done;        // ditto

// Non-contractable f32 ops: mask predicate must be bit-identical to plain IEEE f32
__device__ __forceinline__ float fm(float a, float b) { return __fmul_rn(a, b); }
__device__ __forceinline__ float fa(float a, float b) { return __fadd_rn(a, b); }
__device__ __forceinline__ float fs(float a, float b) { return __fsub_rn(a, b); }

// ---------------- Mask duty: one voxel per thread, 8 blocks per batch ---------------
__device__ void mask_work(int mb, int tid,
                          const float* __restrict__ cq, const float* __restrict__ ck,
                          int* s_cnt)
{
    const int n = mb >> 3;
    const int p = ((mb & 7) << 8) + tid;

    const float x0q = cq[n * 6 + 0], y0q = cq[n * 6 + 1], z0q = cq[n * 6 + 2];
    const float x1q = cq[n * 6 + 3], y1q = cq[n * 6 + 4], z1q = cq[n * 6 + 5];
    const float x0k = ck[n * 6 + 0], y0k = ck[n * 6 + 1], z0k = ck[n * 6 + 2];
    const float x1k = ck[n * 6 + 3], y1k = ck[n * 6 + 4], z1k = ck[n * 6 + 5];

    const float bwq = __fdiv_rn(fs(x1q, x0q), (float)WW);
    const float bhq = __fdiv_rn(fs(y1q, y0q), (float)HH);
    const float bdq = __fdiv_rn(fs(z1q, z0q), (float)DD);
    const float bwk = __fdiv_rn(fs(x1k, x0k), (float)WW);
    const float bhk = __fdiv_rn(fs(y1k, y0k), (float)HH);
    const float bdk = __fdiv_rn(fs(z1k, z0k), (float)DD);

    const float diag_q = __fsqrt_rn(fa(fa(fm(bwq, bwq), fm(bhq, bhq)), fm(bdq, bdq)));
    const float diag_k = __fsqrt_rn(fa(fa(fm(bwk, bwk), fm(bhk, bhk)), fm(bdk, bdk)));
    const float maxdiag = fmaxf(diag_q, diag_k);

    // Candidate windows (widened; fast divides OK — exact predicate filters inside)
    const float r  = 0.5f * maxdiag;
    const float hx = __fdividef(r, bwk) + 0.02f;
    const float hy = __fdividef(r, bhk) + 0.02f;
    const float hz = __fdividef(r, bdk) + 0.02f;

    const int ix = p & 15, iy = (p >> 4) & 15, iz = p >> 8;
    const float cxv = fa(fm((float)ix + 0.5f, bwq), x0q);
    const float cyv = fa(fm((float)iy + 0.5f, bhq), y0q);
    const float czv = fa(fm((float)iz + 0.5f, bdq), z0q);

    const float txc = __fdividef(cxv - x0k, bwk) - 0.5f;
    const float tyc = __fdividef(cyv - y0k, bhk) - 0.5f;
    const float tzc = __fdividef(czv - z0k, bdk) - 0.5f;
    const int jxlo = max(0, (int)ceilf(txc - hx));
    const int jxhi = min(WW - 1, (int)floorf(txc + hx));
    const int jylo = max(0, (int)ceilf(tyc - hy));
    const int jyhi = min(HH - 1, (int)floorf(tyc + hy));
    const int jzlo = max(0, (int)ceilf(tzc - hz));
    const int jzhi = min(DD - 1, (int)floorf(tzc + hz));

    const int base16 = (n * PP + p) * 8;
    int nr = 0, cnt = 0;

    for (int jz = jzlo; jz <= jzhi; jz++) {
        const float dz  = fs(czv, fa(fm((float)jz + 0.5f, bdk), z0k));
        const float dz2 = fm(dz, dz);
        for (int jy = jylo; jy <= jyhi; jy++) {
            const float dy  = fs(cyv, fa(fm((float)jy + 0.5f, bhk), y0k));
            const float dy2 = fm(dy, dy);
            int first = -1, last = -2;
            for (int jx = jxlo; jx <= jxhi; jx++) {
                const float dx = fs(cxv, fa(fm((float)jx + 0.5f, bwk), x0k));
                const float s2 = fa(fa(fm(dx, dx), dy2), dz2);
                // exact reference predicate: sqrt then divide then compare
                if (__fdiv_rn(__fsqrt_rn(s2), maxdiag) < 0.5f) {
                    if (first < 0) first = jx;
                    last = jx;
                }
            }
            if (first >= 0) {
                const int len = last - first + 1;   // <=3 (x-passing set is an interval)
                cnt += len;
                nr++;
                g_runs16[base16 + nr] =
                    (unsigned short)(((jz << 8) + (jy << 4) + first) | (len << 11));
            }
        }
    }
    g_runs16[base16] = (unsigned short)nr;

    s_cnt[tid] = cnt;
    __syncthreads();
    #pragma unroll
    for (int s = 128; s > 0; s >>= 1) {
        if (tid < s) s_cnt[tid] += s_cnt[tid + s];
        __syncthreads();
    }
    if (tid == 0) g_blkcnt[mb] = s_cnt[0];
}

// ---------------- Fused kernel: mask (first 64 blocks) + grouped dot + final --------
__global__ void __launch_bounds__(256) pixpro_fused(
    const float* __restrict__ q, const float* __restrict__ k,
    const float* __restrict__ cq, const float* __restrict__ ck,
    float* __restrict__ out)
{
    const int bx  = blockIdx.x;
    const int tid = threadIdx.x;
    const int n   = bx >> 6;           // 64 blocks per batch
    const int c0  = (bx & 63) << 2;    // first of 4 channels

    __shared__ float4 ks4[PP];         // 32 KB: 4 channels interleaved per voxel
    __shared__ int    s_cnt[256];
    __shared__ float  s_wred[8][G];
    __shared__ int    s_elect;
    __shared__ float  s_loss[NB];

    // Phase 0: mask duty (blocks 0..63), publish before anything else
    if (bx < NMASK) {
        mask_work(bx, tid, cq, ck, s_cnt);
        if (tid == 0) { __threadfence(); atomicAdd(&g_mask_flag, 1); }
    }

    // Phase 1: stage k (4 channels -> float4-interleaved SMEM, conflict-free STS.128)
    const size_t kbase = (size_t)(n * CH + c0) * PP;
    #pragma unroll
    for (int j = 0; j < 8; j++) {
        const int i = tid + (j << 8);
        float4 v;
        v.x = __ldg(k + kbase + i);
        v.y = __ldg(k + kbase + PP + i);
        v.z = __ldg(k + kbase + 2 * PP + i);
        v.w = __ldg(k + kbase + 3 * PP + i);
        ks4[i] = v;
    }

    // Phase 2: wait for all mask blocks (deadlock-safe: >=148 resident >= 64)
    if (tid == 0) {
        while (*(volatile int*)&g_mask_flag < NMASK) __nanosleep(64);
    }
    __syncthreads();

    // Phase 3: masked dot for 4 channels
    const uint4* __restrict__ rp =
        reinterpret_cast<const uint4*>(g_runs16) + (size_t)n * PP;
    const float* __restrict__ qp = q + (size_t)(n * CH + c0) * PP;

    float l0 = 0.f, l1 = 0.f, l2 = 0.f, l3 = 0.f;
    #pragma unroll
    for (int j = 0; j < 8; j++) {
        const int p = tid + (j << 8);
        const uint4 h = __ldcg(rp + p);       // L2-only: fresh run records
        const float q0 = __ldg(qp + p);
        const float q1 = __ldg(qp + PP + p);
        const float q2 = __ldg(qp + 2 * PP + p);
        const float q3 = __ldg(qp + 3 * PP + p);
        const int nr = (int)(h.x & 0xFFFFu);
        float a0 = 0.f, a1 = 0.f, a2 = 0.f, a3 = 0.f;
        #pragma unroll
        for (int s = 1; s <= 6; s++) {
            const unsigned w = (s < 2) ? h.x : ((s < 4) ? h.y : ((s < 6) ? h.z : h.w));
            const unsigned run = (s & 1) ? (w >> 16) : (w & 0xFFFFu);
            const int base = (int)(run & 0x7FFu);
            const int len  = (int)((run >> 11) & 0x3u);
            if (s <= nr) {
                float4 v = ks4[base];
                a0 += v.x; a1 += v.y; a2 += v.z; a3 += v.w;
                if (len > 1) { float4 u = ks4[base + 1]; a0 += u.x; a1 += u.y; a2 += u.z; a3 += u.w; }
                if (len > 2) { float4 u = ks4[base + 2]; a0 += u.x; a1 += u.y; a2 += u.z; a3 += u.w; }
            }
        }
        l0 = fmaf(q0, a0, l0);
        l1 = fmaf(q1, a1, l1);
        l2 = fmaf(q2, a2, l2);
        l3 = fmaf(q3, a3, l3);
    }

    // Per-channel deterministic reduction (warp shuffle + fixed-order cross-warp)
    #pragma unroll
    for (int off = 16; off > 0; off >>= 1) {
        l0 += __shfl_down_sync(0xFFFFFFFFu, l0, off);
        l1 += __shfl_down_sync(0xFFFFFFFFu, l1, off);
        l2 += __shfl_down_sync(0xFFFFFFFFu, l2, off);
        l3 += __shfl_down_sync(0xFFFFFFFFu, l3, off);
    }
    if ((tid & 31) == 0) {
        const int w = tid >> 5;
        s_wred[w][0] = l0; s_wred[w][1] = l1; s_wred[w][2] = l2; s_wred[w][3] = l3;
    }
    __syncthreads();

    // tid 0 writes all 4 partials itself (so its threadfence orders them), then ticket
    if (tid == 0) {
        #pragma unroll
        for (int g = 0; g < G; g++) {
            float s = 0.f;
            #pragma unroll
            for (int w = 0; w < 8; w++) s += s_wred[w][g];
            g_partials[n * CH + c0 + g] = s;
        }
        __threadfence();
        s_elect = (atomicAdd(&g_done, 1) == NBLK - 1) ? 1 : 0;
    }
    __syncthreads();

    // Phase 4: last-done block finalizes (fixed-order, deterministic)
    if (s_elect) {
        const int w    = tid >> 5;   // batch index
        const int lane = tid & 31;
        float s = 0.f;
        #pragma unroll
        for (int j = 0; j < 8; j++)
            s += __ldcg(&g_partials[w * CH + j * 32 + lane]);
        #pragma unroll
        for (int off = 16; off > 0; off >>= 1)
            s += __shfl_down_sync(0xFFFFFFFFu, s, off);
        if (lane == 0) {
            int cnt = 0;
            #pragma unroll
            for (int b = 0; b < 8; b++) cnt += __ldcg(&g_blkcnt[w * 8 + b]);
            s_loss[w] = s / ((float)cnt + 1e-6f);
        }
        __syncthreads();
        if (tid == 0) {
            float m = 0.f;
            #pragma unroll
            for (int i = 0; i < NB; i++) m += s_loss[i];
            out[0] = -2.0f * (m * (1.0f / (float)NB));
            // self-reset for next graph replay (all blocks already ticketed)
            g_mask_flag = 0;
            g_done = 0;
        }
    }
}

extern "C" void kernel_launch(void* const* d_in, const int* in_sizes, int n_in,
                              void* d_out, int out_size)
{
    const float* q  = (const float*)d_in[0];
    const float* k  = (const float*)d_in[1];
    const float* cq = (const float*)d_in[2];
    const float* ck = (const float*)d_in[3];
    float* out = (float*)d_out;

    pixpro_fused<<<NBLK, 256>>>(q, k, cq, ck, out);
}

// round 5
// speedup vs baseline: 4.6112x; 1.1577x over previous
#include <cuda_runtime.h>

// Problem constants (fixed by setup_inputs)
#define NB 8
#define CH 256
#define DD 8
#define HH 16
#define WW 16
#define PP 2048            // DD*HH*WW
#define G  4               // channels per block
#define NBLK (NB * (CH / G))   // 512 blocks, 64 per batch

// Scratch (no allocations allowed)
__device__ float g_partials[NB * CH];
__device__ int   g_cnt[NB];        // per-batch mask counts (int atomics: deterministic)
// Per-voxel run records: 8 x u16: slot0=nruns; slots1..6: bits[0:11)=base, [11:13)=len(1..3)
__device__ __align__(16) unsigned short g_runs16[NB * PP * 8];
__device__ int g_mask_flag[NB];    // chunks done per batch (64 each); reset at end
__device__ int g_done;             // completion ticket; reset at end

// Non-contractable f32 ops: mask predicate must be bit-identical to plain IEEE f32
__device__ __forceinline__ float fm(float a, float b) { return __fmul_rn(a, b); }
__device__ __forceinline__ float fa(float a, float b) { return __fadd_rn(a, b); }
__device__ __forceinline__ float fs(float a, float b) { return __fsub_rn(a, b); }

// ---------------- Mask duty: warp 0 of every block, one voxel per lane ---------------
// Returns this lane's positive count.
__device__ __forceinline__ int mask_voxel(
    int n, int p, const float* __restrict__ cq, const float* __restrict__ ck)
{
    const float x0q = cq[n * 6 + 0], y0q = cq[n * 6 + 1], z0q = cq[n * 6 + 2];
    const float x1q = cq[n * 6 + 3], y1q = cq[n * 6 + 4], z1q = cq[n * 6 + 5];
    const float x0k = ck[n * 6 + 0], y0k = ck[n * 6 + 1], z0k = ck[n * 6 + 2];
    const float x1k = ck[n * 6 + 3], y1k = ck[n * 6 + 4], z1k = ck[n * 6 + 5];

    const float bwq = __fdiv_rn(fs(x1q, x0q), (float)WW);
    const float bhq = __fdiv_rn(fs(y1q, y0q), (float)HH);
    const float bdq = __fdiv_rn(fs(z1q, z0q), (float)DD);
    const float bwk = __fdiv_rn(fs(x1k, x0k), (float)WW);
    const float bhk = __fdiv_rn(fs(y1k, y0k), (float)HH);
    const float bdk = __fdiv_rn(fs(z1k, z0k), (float)DD);

    const float diag_q = __fsqrt_rn(fa(fa(fm(bwq, bwq), fm(bhq, bhq)), fm(bdq, bdq)));
    const float diag_k = __fsqrt_rn(fa(fa(fm(bwk, bwk), fm(bhk, bhk)), fm(bdk, bdk)));
    const float maxdiag = fmaxf(diag_q, diag_k);

    // Candidate windows (widened; fast divides OK — exact predicate filters inside)
    const float r  = 0.5f * maxdiag;
    const float hx = __fdividef(r, bwk) + 0.02f;
    const float hy = __fdividef(r, bhk) + 0.02f;
    const float hz = __fdividef(r, bdk) + 0.02f;

    const int ix = p & 15, iy = (p >> 4) & 15, iz = p >> 8;
    const float cxv = fa(fm((float)ix + 0.5f, bwq), x0q);
    const float cyv = fa(fm((float)iy + 0.5f, bhq), y0q);
    const float czv = fa(fm((float)iz + 0.5f, bdq), z0q);

    const float txc = __fdividef(cxv - x0k, bwk) - 0.5f;
    const float tyc = __fdividef(cyv - y0k, bhk) - 0.5f;
    const float tzc = __fdividef(czv - z0k, bdk) - 0.5f;
    const int jxlo = max(0, (int)ceilf(txc - hx));
    const int jxhi = min(WW - 1, (int)floorf(txc + hx));
    const int jylo = max(0, (int)ceilf(tyc - hy));
    const int jyhi = min(HH - 1, (int)floorf(tyc + hy));
    const int jzlo = max(0, (int)ceilf(tzc - hz));
    const int jzhi = min(DD - 1, (int)floorf(tzc + hz));

    const int base16 = (n * PP + p) * 8;
    int nr = 0, cnt = 0;

    for (int jz = jzlo; jz <= jzhi; jz++) {
        const float dz  = fs(czv, fa(fm((float)jz + 0.5f, bdk), z0k));
        const float dz2 = fm(dz, dz);
        for (int jy = jylo; jy <= jyhi; jy++) {
            const float dy  = fs(cyv, fa(fm((float)jy + 0.5f, bhk), y0k));
            const float dy2 = fm(dy, dy);
            int first = -1, last = -2;
            for (int jx = jxlo; jx <= jxhi; jx++) {
                const float dx = fs(cxv, fa(fm((float)jx + 0.5f, bwk), x0k));
                const float s2 = fa(fa(fm(dx, dx), dy2), dz2);
                // exact reference predicate: sqrt then divide then compare
                if (__fdiv_rn(__fsqrt_rn(s2), maxdiag) < 0.5f) {
                    if (first < 0) first = jx;
                    last = jx;
                }
            }
            if (first >= 0) {
                const int len = last - first + 1;   // <=3 (x-passing set is an interval)
                cnt += len;
                nr++;
                g_runs16[base16 + nr] =
                    (unsigned short)(((jz << 8) + (jy << 4) + first) | (len << 11));
            }
        }
    }
    g_runs16[base16] = (unsigned short)nr;
    return cnt;
}

// ---------------- Fused kernel --------------------------------------------------------
__global__ void __launch_bounds__(256) pixpro_fused(
    const float* __restrict__ q, const float* __restrict__ k,
    const float* __restrict__ cq, const float* __restrict__ ck,
    float* __restrict__ out)
{
    const int bx  = blockIdx.x;
    const int tid = threadIdx.x;
    const int n   = bx >> 6;           // 64 blocks per batch
    const int c0  = (bx & 63) << 2;    // first of 4 channels

    __shared__ float4 ks4[PP];         // 32 KB: 4 channels interleaved per voxel
    __shared__ float  s_wred[8][G];
    __shared__ int    s_elect;
    __shared__ float  s_loss[NB];

    // Phase 0: mask duty — warp 0 only, one voxel per lane (32 voxels per block).
    // Block bx's chunk [bx*32, bx*32+32) lies inside its own batch n.
    if (tid < 32) {
        const int p = ((bx & 63) << 5) + tid;
        int cnt = mask_voxel(n, p, cq, ck);
        #pragma unroll
        for (int off = 16; off > 0; off >>= 1)
            cnt += __shfl_down_sync(0xFFFFFFFFu, cnt, off);
        __syncwarp();
        if (tid == 0) {
            if (cnt) atomicAdd(&g_cnt[n], cnt);
            __threadfence();
            atomicAdd(&g_mask_flag[n], 1);
        }
    }

    // Phase 1: stage k (4 channels -> float4-interleaved SMEM, conflict-free STS.128)
    const size_t kbase = (size_t)(n * CH + c0) * PP;
    #pragma unroll
    for (int j = 0; j < 8; j++) {
        const int i = tid + (j << 8);
        float4 v;
        v.x = __ldg(k + kbase + i);
        v.y = __ldg(k + kbase + PP + i);
        v.z = __ldg(k + kbase + 2 * PP + i);
        v.w = __ldg(k + kbase + 3 * PP + i);
        ks4[i] = v;
    }

    // Phase 2: wait for this batch's 64 mask chunks (all 512 blocks co-resident:
    // 6 blocks/SM by smem/regs -> capacity 888 >= 512; publishers publish first)
    if (tid == 0) {
        while (*(volatile int*)&g_mask_flag[n] < 64) __nanosleep(32);
        __threadfence();
    }
    __syncthreads();

    // Phase 3: masked dot for 4 channels
    const uint4* __restrict__ rp =
        reinterpret_cast<const uint4*>(g_runs16) + (size_t)n * PP;
    const float* __restrict__ qp = q + (size_t)(n * CH + c0) * PP;

    float l0 = 0.f, l1 = 0.f, l2 = 0.f, l3 = 0.f;
    #pragma unroll
    for (int j = 0; j < 8; j++) {
        const int p = tid + (j << 8);
        const uint4 h = __ldcg(rp + p);       // L2-only: fresh run records
        const float q0 = __ldg(qp + p);
        const float q1 = __ldg(qp + PP + p);
        const float q2 = __ldg(qp + 2 * PP + p);
        const float q3 = __ldg(qp + 3 * PP + p);
        const int nr = (int)(h.x & 0xFFFFu);
        float a0 = 0.f, a1 = 0.f, a2 = 0.f, a3 = 0.f;
        #pragma unroll
        for (int s = 1; s <= 6; s++) {
            const unsigned w = (s < 2) ? h.x : ((s < 4) ? h.y : ((s < 6) ? h.z : h.w));
            const unsigned run = (s & 1) ? (w >> 16) : (w & 0xFFFFu);
            const int base = (int)(run & 0x7FFu);
            const int len  = (int)((run >> 11) & 0x3u);
            if (s <= nr) {
                float4 v = ks4[base];
                a0 += v.x; a1 += v.y; a2 += v.z; a3 += v.w;
                if (len > 1) { float4 u = ks4[base + 1]; a0 += u.x; a1 += u.y; a2 += u.z; a3 += u.w; }
                if (len > 2) { float4 u = ks4[base + 2]; a0 += u.x; a1 += u.y; a2 += u.z; a3 += u.w; }
            }
        }
        l0 = fmaf(q0, a0, l0);
        l1 = fmaf(q1, a1, l1);
        l2 = fmaf(q2, a2, l2);
        l3 = fmaf(q3, a3, l3);
    }

    // Per-channel deterministic reduction (warp shuffle + fixed-order cross-warp)
    #pragma unroll
    for (int off = 16; off > 0; off >>= 1) {
        l0 += __shfl_down_sync(0xFFFFFFFFu, l0, off);
        l1 += __shfl_down_sync(0xFFFFFFFFu, l1, off);
        l2 += __shfl_down_sync(0xFFFFFFFFu, l2, off);
        l3 += __shfl_down_sync(0xFFFFFFFFu, l3, off);
    }
    if ((tid & 31) == 0) {
        const int w = tid >> 5;
        s_wred[w][0] = l0; s_wred[w][1] = l1; s_wred[w][2] = l2; s_wred[w][3] = l3;
    }
    __syncthreads();

    // tid 0 writes all 4 partials (so its threadfence orders them), then tickets
    if (tid == 0) {
        #pragma unroll
        for (int g = 0; g < G; g++) {
            float s = 0.f;
            #pragma unroll
            for (int w = 0; w < 8; w++) s += s_wred[w][g];
            g_partials[n * CH + c0 + g] = s;
        }
        __threadfence();
        s_elect = (atomicAdd(&g_done, 1) == NBLK - 1) ? 1 : 0;
    }
    __syncthreads();

    // Phase 4: last-done block finalizes (fixed-order, deterministic)
    if (s_elect) {
        const int w    = tid >> 5;   // batch index
        const int lane = tid & 31;
        float s = 0.f;
        #pragma unroll
        for (int j = 0; j < 8; j++)
            s += __ldcg(&g_partials[w * CH + j * 32 + lane]);
        #pragma unroll
        for (int off = 16; off > 0; off >>= 1)
            s += __shfl_down_sync(0xFFFFFFFFu, s, off);
        if (lane == 0)
            s_loss[w] = s / ((float)__ldcg(&g_cnt[w]) + 1e-6f);
        __syncthreads();
        if (tid == 0) {
            float m = 0.f;
            #pragma unroll
            for (int i = 0; i < NB; i++) m += s_loss[i];
            out[0] = -2.0f * (m * (1.0f / (float)NB));
            // self-reset for next graph replay (all blocks already ticketed)
            #pragma unroll
            for (int i = 0; i < NB; i++) { g_mask_flag[i] = 0; g_cnt[i] = 0; }
            g_done = 0;
        }
    }
}

extern "C" void kernel_launch(void* const* d_in, const int* in_sizes, int n_in,
                              void* d_out, int out_size)
{
    const float* q  = (const float*)d_in[0];
    const float* k  = (const float*)d_in[1];
    const float* cq = (const float*)d_in[2];
    const float* ck = (const float*)d_in[3];
    float* out = (float*)d_out;

    pixpro_fused<<<NBLK, 256>>>(q, k, cq, ck, out);
}